// round 3
// baseline (speedup 1.0000x reference)
#include <cuda_runtime.h>
#include <cuda_bf16.h>

// Problem constants (fixed by the reference).
#define LSEQ 8192
#define EDIM 256
#define HDIM 256      // per-direction hidden
#define G4   1024     // 4*HDIM gate rows
#define KTAG 10
#define NBLK 16       // blocks per direction in the recurrence
#define TAG_START 8
#define TAG_STOP  9

// ---------------------------------------------------------------------------
// Scratch (static device globals: allocation-free per harness rules)
// ---------------------------------------------------------------------------
__device__ float g_P[2][LSEQ][G4];      // input projections + biases, per dir
__device__ float g_h[2][LSEQ][HDIM];    // hidden states per position, per dir
__device__ float g_feats[LSEQ][KTAG];   // emission scores
__device__ int   g_cnt[2][LSEQ];        // per-step arrival counters (recurrence sync)

__device__ __forceinline__ float tanh_fast(float x) {
    float y;
    asm("tanh.approx.f32 %0, %1;" : "=f"(y) : "f"(x));
    return y;
}
__device__ __forceinline__ float sig_fast(float x) {
    return 0.5f * tanh_fast(0.5f * x) + 0.5f;
}

// ---------------------------------------------------------------------------
// Zero the sync counters (must be re-zeroed every launch for graph replay)
// ---------------------------------------------------------------------------
__global__ void zero_cnt_kernel() {
    int i = blockIdx.x * blockDim.x + threadIdx.x;
    if (i < 2 * LSEQ) (&g_cnt[0][0])[i] = 0;
}

// ---------------------------------------------------------------------------
// Input projection GEMM with fused embedding gather:
//   P[dir][m][n] = sum_k emb[sent[m]][k] * Wih[dir][n][k] + bih[n] + bhh[n]
// Tiles: BM=64, BN=64, BK=32; 256 threads; 4x4 microtile per thread.
// ---------------------------------------------------------------------------
__global__ __launch_bounds__(256) void proj_kernel(
    const int* __restrict__ sent, const float* __restrict__ emb,
    const float* __restrict__ Wf, const float* __restrict__ bfa, const float* __restrict__ bfb,
    const float* __restrict__ Wb, const float* __restrict__ bba, const float* __restrict__ bbb)
{
    const int dir = blockIdx.z;
    const float* W  = dir ? Wb  : Wf;
    const float* b1 = dir ? bba : bfa;
    const float* b2 = dir ? bbb : bfb;
    float* P = &g_P[dir][0][0];

    __shared__ float As[32][72];   // [k][m], padded: 72*4B = 288B rows (16B aligned)
    __shared__ float Bs[32][72];   // [k][n]

    const int tid = threadIdx.x;
    const int tx = tid & 15, ty = tid >> 4;
    const int m0 = blockIdx.x * 64, n0 = blockIdx.y * 64;

    float acc[4][4];
#pragma unroll
    for (int i = 0; i < 4; i++)
#pragma unroll
        for (int j = 0; j < 4; j++) acc[i][j] = 0.f;

    for (int kb = 0; kb < EDIM; kb += 32) {
#pragma unroll
        for (int i = 0; i < 2; i++) {
            int slot = tid + i * 256;        // 512 slots = 64 rows x 8 float4
            int ml = slot >> 3, k4 = slot & 7;
            int row = sent[m0 + ml];
            float4 av = *reinterpret_cast<const float4*>(&emb[row * EDIM + kb + k4 * 4]);
            As[k4 * 4 + 0][ml] = av.x; As[k4 * 4 + 1][ml] = av.y;
            As[k4 * 4 + 2][ml] = av.z; As[k4 * 4 + 3][ml] = av.w;
            float4 wv = *reinterpret_cast<const float4*>(&W[(n0 + ml) * EDIM + kb + k4 * 4]);
            Bs[k4 * 4 + 0][ml] = wv.x; Bs[k4 * 4 + 1][ml] = wv.y;
            Bs[k4 * 4 + 2][ml] = wv.z; Bs[k4 * 4 + 3][ml] = wv.w;
        }
        __syncthreads();
#pragma unroll
        for (int kk = 0; kk < 32; kk++) {
            float4 a = *reinterpret_cast<const float4*>(&As[kk][ty * 4]);
            float4 b = *reinterpret_cast<const float4*>(&Bs[kk][tx * 4]);
            float av[4] = {a.x, a.y, a.z, a.w};
            float bv[4] = {b.x, b.y, b.z, b.w};
#pragma unroll
            for (int i = 0; i < 4; i++)
#pragma unroll
                for (int j = 0; j < 4; j++) acc[i][j] += av[i] * bv[j];
        }
        __syncthreads();
    }

    float bsum[4];
#pragma unroll
    for (int j = 0; j < 4; j++) bsum[j] = b1[n0 + tx * 4 + j] + b2[n0 + tx * 4 + j];
#pragma unroll
    for (int i = 0; i < 4; i++) {
        float4 o;
        o.x = acc[i][0] + bsum[0]; o.y = acc[i][1] + bsum[1];
        o.z = acc[i][2] + bsum[2]; o.w = acc[i][3] + bsum[3];
        *reinterpret_cast<float4*>(&P[(m0 + ty * 4 + i) * G4 + n0 + tx * 4]) = o;
    }
}

// ---------------------------------------------------------------------------
// Persistent LSTM recurrence. 2*NBLK blocks, 256 threads each.
// Block (dir, b) owns hidden units [b*16, b*16+16) of direction dir.
// Thread tid = u*16 + g*4 + c: unit u (0..15), gate g (0..3), col-quarter c.
// Each thread holds 64 Whh weights in registers (row g*256+j0+u, cols c*64..+63).
// Cross-block sync: release(STG h -> fence -> atomicAdd cnt[s]) /
//                   acquire(volatile poll cnt -> fence -> ldcg h).
// ---------------------------------------------------------------------------
__global__ __launch_bounds__(256) void lstm_kernel(
    const float* __restrict__ Whh_f, const float* __restrict__ Whh_b)
{
    const int dir = blockIdx.x / NBLK;
    const int b   = blockIdx.x % NBLK;
    const float* Whh = dir ? Whh_b : Whh_f;
    const float* P = &g_P[dir][0][0];
    float* hs = &g_h[dir][0][0];
    int* cnt = &g_cnt[dir][0];

    const int tid = threadIdx.x;
    const int u = tid >> 4, g = (tid >> 2) & 3, c = tid & 3;
    const int j0 = b * 16;
    const int r = g * 256 + j0 + u;           // gate row in [0, 1024)

    // Preload weights into registers, chunk-rotated by (k'+c)&15 so the
    // matching smem float4 reads are bank-conflict-free.
    float w[64];
    {
        const float4* wrow4 = reinterpret_cast<const float4*>(Whh + r * HDIM + c * 64);
#pragma unroll
        for (int kq = 0; kq < 16; kq++) {
            int ch = (kq + c) & 15;
            float4 t = wrow4[ch];
            w[4 * kq + 0] = t.x; w[4 * kq + 1] = t.y;
            w[4 * kq + 2] = t.z; w[4 * kq + 3] = t.w;
        }
    }

    __shared__ float sh[HDIM];
    __shared__ float sgate[64];

    float creg = 0.f;   // cell state for unit (tid<16 lanes only)

    for (int s = 0; s < LSEQ; s++) {
        const int pos = dir ? (LSEQ - 1 - s) : s;

        // Prefetch the precomputed input projection (independent of the sync).
        float pv = 0.f;
        if (c == 0) pv = __ldg(&P[pos * G4 + r]);

        // Acquire h[t-1] from all peer blocks.
        if (s > 0) {
            if (tid == 0) {
                volatile int* vp = cnt + (s - 1);
                while (*vp < NBLK) { }
                __threadfence();
            }
            __syncthreads();
            const int prevpos = dir ? (pos + 1) : (pos - 1);
            sh[tid] = __ldcg(&hs[prevpos * HDIM + tid]);
        } else {
            sh[tid] = 0.f;
        }
        __syncthreads();

        // Recurrent partial dot: 16 LDS.128 + 64 FFMA from registers.
        float part = 0.f;
        const float4* sh4 = reinterpret_cast<const float4*>(sh + c * 64);
#pragma unroll
        for (int kq = 0; kq < 16; kq++) {
            int ch = (kq + c) & 15;
            float4 hv = sh4[ch];
            part += w[4 * kq + 0] * hv.x + w[4 * kq + 1] * hv.y
                  + w[4 * kq + 2] * hv.z + w[4 * kq + 3] * hv.w;
        }
        // Reduce across the 4 column-quarters (contiguous lanes).
        part += __shfl_down_sync(0xFFFFFFFFu, part, 2, 4);
        part += __shfl_down_sync(0xFFFFFFFFu, part, 1, 4);
        if (c == 0) sgate[u * 4 + g] = part + pv;
        __syncthreads();

        // Cell/hidden update + release.
        if (tid < 16) {
            float gi = sgate[tid * 4 + 0];
            float gf = sgate[tid * 4 + 1];
            float gg = sgate[tid * 4 + 2];
            float go = sgate[tid * 4 + 3];
            creg = sig_fast(gf) * creg + sig_fast(gi) * tanh_fast(gg);
            float hv = sig_fast(go) * tanh_fast(creg);
            hs[pos * HDIM + j0 + tid] = hv;
            __threadfence();
        }
        __syncthreads();
        if (tid == 0) atomicAdd(cnt + s, 1);
    }
}

// ---------------------------------------------------------------------------
// feats[t][k] = [hf[t], hb[t]] . W_tag[k] + b_tag[k]
// One block of 64 threads per position; warp w handles tags w*5..w*5+4.
// ---------------------------------------------------------------------------
__global__ __launch_bounds__(64) void feats_kernel(
    const float* __restrict__ Wtag, const float* __restrict__ btag)
{
    __shared__ float shc[512];
    const int t = blockIdx.x;
    const int tid = threadIdx.x;
#pragma unroll
    for (int i = 0; i < 8; i++) {
        int d = tid + 64 * i;
        shc[d] = (d < HDIM) ? g_h[0][t][d] : g_h[1][t][d - HDIM];
    }
    __syncthreads();
    const int wr = tid >> 5, l = tid & 31;
#pragma unroll
    for (int kk = 0; kk < 5; kk++) {
        int k = wr * 5 + kk;
        float ssum = 0.f;
#pragma unroll
        for (int j = 0; j < 16; j++) {
            int d = l + 32 * j;
            ssum += shc[d] * Wtag[k * 512 + d];
        }
#pragma unroll
        for (int off = 16; off >= 1; off >>= 1)
            ssum += __shfl_down_sync(0xFFFFFFFFu, ssum, off);
        if (l == 0) g_feats[t][k] = ssum + btag[k];
    }
}

// ---------------------------------------------------------------------------
// Viterbi max-plus scan + traceback. One warp. Backpointers in dynamic smem
// (80 KB) so the sequential traceback is an smem pointer-chase.
// Argmax: strict '>' with ascending index == jnp.argmax first-max semantics.
// ---------------------------------------------------------------------------
__global__ void viterbi_kernel(const float* __restrict__ trans,
                               float* __restrict__ out, int out_size)
{
    extern __shared__ unsigned char bp[];   // [LSEQ][KTAG]
    const int lane = threadIdx.x;
    const int j = lane < KTAG ? lane : KTAG - 1;

    float Trow[KTAG];
#pragma unroll
    for (int p = 0; p < KTAG; p++) Trow[p] = trans[j * KTAG + p];

    float v = (lane == TAG_START) ? 0.f : -10000.f;
    float fc = g_feats[0][j];

    for (int t = 0; t < LSEQ; t++) {
        float fn = (t + 1 < LSEQ) ? g_feats[t + 1][j] : 0.f;   // prefetch
        float best = -3.4e38f;
        int arg = 0;
#pragma unroll
        for (int p = 0; p < KTAG; p++) {
            float vp = __shfl_sync(0xFFFFFFFFu, v, p);
            float cand = vp + Trow[p];
            if (cand > best) { best = cand; arg = p; }
        }
        if (lane < KTAG) bp[t * KTAG + lane] = (unsigned char)arg;
        v = best + fc;
        fc = fn;
    }

    float term = v + trans[TAG_STOP * KTAG + j];
    float bbest = -3.4e38f;
    int barg = 0;
#pragma unroll
    for (int p = 0; p < KTAG; p++) {
        float tp = __shfl_sync(0xFFFFFFFFu, term, p);
        if (tp > bbest) { bbest = tp; barg = p; }
    }
    __syncwarp();

    if (lane == 0) {
        if (out_size > 0) out[0] = bbest;                 // score
        int tag = barg;
        if (out_size > LSEQ) out[LSEQ] = (float)tag;      // path[L-1]
        for (int t = LSEQ - 1; t >= 1; t--) {
            tag = bp[t * KTAG + tag];
            if (out_size > t) out[t] = (float)tag;        // path[t-1] at index t
        }
    }
}

// ---------------------------------------------------------------------------
// Launch
// ---------------------------------------------------------------------------
extern "C" void kernel_launch(void* const* d_in, const int* in_sizes, int n_in,
                              void* d_out, int out_size)
{
    const int*   sent  = (const int*)  d_in[0];
    const float* emb   = (const float*)d_in[1];
    const float* Wih_f = (const float*)d_in[2];
    const float* Whh_f = (const float*)d_in[3];
    const float* bih_f = (const float*)d_in[4];
    const float* bhh_f = (const float*)d_in[5];
    const float* Wih_b = (const float*)d_in[6];
    const float* Whh_b = (const float*)d_in[7];
    const float* bih_b = (const float*)d_in[8];
    const float* bhh_b = (const float*)d_in[9];
    const float* W_tag = (const float*)d_in[10];
    const float* b_tag = (const float*)d_in[11];
    const float* trans = (const float*)d_in[12];
    float* out = (float*)d_out;

    cudaFuncSetAttribute(viterbi_kernel,
                         cudaFuncAttributeMaxDynamicSharedMemorySize,
                         LSEQ * KTAG);

    zero_cnt_kernel<<<(2 * LSEQ + 255) / 256, 256>>>();
    proj_kernel<<<dim3(LSEQ / 64, G4 / 64, 2), 256>>>(
        sent, emb, Wih_f, bih_f, bhh_f, Wih_b, bih_b, bhh_b);
    lstm_kernel<<<2 * NBLK, 256>>>(Whh_f, Whh_b);
    feats_kernel<<<LSEQ, 64>>>(W_tag, b_tag);
    viterbi_kernel<<<1, 32, LSEQ * KTAG>>>(trans, out, out_size);
}

// round 4
// speedup vs baseline: 2.0457x; 2.0457x over previous
#include <cuda_runtime.h>
#include <cuda_bf16.h>
#include <cstdint>

// Problem constants (fixed by the reference).
#define LSEQ 8192
#define EDIM 256
#define HDIM 256      // per-direction hidden
#define G4   1024     // 4*HDIM gate rows
#define KTAG 10
#define NCTA 8        // CTAs per direction = one cluster
#define UPB  32       // hidden units per CTA
#define TXBYTES (7 * 16 * 8)   // 7 peers x 16 st.async.b64 each = 896 bytes/phase
#define TAG_START 8
#define TAG_STOP  9

// ---------------------------------------------------------------------------
// Scratch (static device globals: allocation-free per harness rules)
// ---------------------------------------------------------------------------
__device__ float g_P[2][LSEQ][G4];      // input projections + biases, per dir
__device__ float g_h[2][LSEQ][HDIM];    // hidden states per position, per dir
__device__ float g_feats[LSEQ][KTAG];   // emission scores

__device__ __forceinline__ float tanh_fast(float x) {
    float y;
    asm("tanh.approx.f32 %0, %1;" : "=f"(y) : "f"(x));
    return y;
}
__device__ __forceinline__ float sig_fast(float x) {
    return 0.5f * tanh_fast(0.5f * x) + 0.5f;
}
__device__ __forceinline__ uint32_t smem_u32(const void* p) {
    return (uint32_t)__cvta_generic_to_shared(p);
}
__device__ __forceinline__ uint32_t mapa_rank(uint32_t addr, uint32_t rank) {
    uint32_t r;
    asm("mapa.shared::cluster.u32 %0, %1, %2;" : "=r"(r) : "r"(addr), "r"(rank));
    return r;
}
__device__ __forceinline__ void mbar_wait_parity(uint32_t addr, uint32_t parity) {
    asm volatile(
        "{\n\t"
        ".reg .pred P;\n\t"
        "WLOOP%=:\n\t"
        "mbarrier.try_wait.parity.acquire.cluster.shared::cta.b64 P, [%0], %1;\n\t"
        "@!P bra WLOOP%=;\n\t"
        "}"
        :: "r"(addr), "r"(parity) : "memory");
}

// ---------------------------------------------------------------------------
// Input projection GEMM with fused embedding gather:
//   P[dir][m][n] = sum_k emb[sent[m]][k] * Wih[dir][n][k] + bih[n] + bhh[n]
// ---------------------------------------------------------------------------
__global__ __launch_bounds__(256) void proj_kernel(
    const int* __restrict__ sent, const float* __restrict__ emb,
    const float* __restrict__ Wf, const float* __restrict__ bfa, const float* __restrict__ bfb,
    const float* __restrict__ Wb, const float* __restrict__ bba, const float* __restrict__ bbb)
{
    const int dir = blockIdx.z;
    const float* W  = dir ? Wb  : Wf;
    const float* b1 = dir ? bba : bfa;
    const float* b2 = dir ? bbb : bfb;
    float* P = &g_P[dir][0][0];

    __shared__ float As[32][72];
    __shared__ float Bs[32][72];

    const int tid = threadIdx.x;
    const int tx = tid & 15, ty = tid >> 4;
    const int m0 = blockIdx.x * 64, n0 = blockIdx.y * 64;

    float acc[4][4];
#pragma unroll
    for (int i = 0; i < 4; i++)
#pragma unroll
        for (int j = 0; j < 4; j++) acc[i][j] = 0.f;

    for (int kb = 0; kb < EDIM; kb += 32) {
#pragma unroll
        for (int i = 0; i < 2; i++) {
            int slot = tid + i * 256;
            int ml = slot >> 3, k4 = slot & 7;
            int row = sent[m0 + ml];
            float4 av = *reinterpret_cast<const float4*>(&emb[row * EDIM + kb + k4 * 4]);
            As[k4 * 4 + 0][ml] = av.x; As[k4 * 4 + 1][ml] = av.y;
            As[k4 * 4 + 2][ml] = av.z; As[k4 * 4 + 3][ml] = av.w;
            float4 wv = *reinterpret_cast<const float4*>(&W[(n0 + ml) * EDIM + kb + k4 * 4]);
            Bs[k4 * 4 + 0][ml] = wv.x; Bs[k4 * 4 + 1][ml] = wv.y;
            Bs[k4 * 4 + 2][ml] = wv.z; Bs[k4 * 4 + 3][ml] = wv.w;
        }
        __syncthreads();
#pragma unroll
        for (int kk = 0; kk < 32; kk++) {
            float4 a = *reinterpret_cast<const float4*>(&As[kk][ty * 4]);
            float4 b = *reinterpret_cast<const float4*>(&Bs[kk][tx * 4]);
            float av[4] = {a.x, a.y, a.z, a.w};
            float bv[4] = {b.x, b.y, b.z, b.w};
#pragma unroll
            for (int i = 0; i < 4; i++)
#pragma unroll
                for (int j = 0; j < 4; j++) acc[i][j] += av[i] * bv[j];
        }
        __syncthreads();
    }

    float bsum[4];
#pragma unroll
    for (int j = 0; j < 4; j++) bsum[j] = b1[n0 + tx * 4 + j] + b2[n0 + tx * 4 + j];
#pragma unroll
    for (int i = 0; i < 4; i++) {
        float4 o;
        o.x = acc[i][0] + bsum[0]; o.y = acc[i][1] + bsum[1];
        o.z = acc[i][2] + bsum[2]; o.w = acc[i][3] + bsum[3];
        *reinterpret_cast<float4*>(&P[(m0 + ty * 4 + i) * G4 + n0 + tx * 4]) = o;
    }
}

// ---------------------------------------------------------------------------
// Persistent LSTM recurrence over DSMEM.
// Grid = 16 CTAs, cluster 8: cluster 0 = dir 0, cluster 1 = dir 1.
// CTA rank owns units [rank*32, rank*32+32) = 128 gate rows; 512 threads.
// Thread tid = u*16 + g*4 + c: unit u, gate g, column-quarter c; 64 weight
// floats per thread held as 32 packed f32x2 registers.
// h exchange: double-buffered sh[2][256]; producers stage locally, 112 sender
// threads st.async.b64 into the 7 peers (tx-counted on the remote mbarrier);
// consumers try_wait.parity.acquire.cluster.
// ---------------------------------------------------------------------------
__global__ void __cluster_dims__(NCTA, 1, 1) __launch_bounds__(512, 1)
lstm_kernel(const float* __restrict__ Whh_f, const float* __restrict__ Whh_b)
{
    const int dir = blockIdx.x >> 3;
    uint32_t myrank;
    asm("mov.u32 %0, %%cluster_ctarank;" : "=r"(myrank));
    const float* __restrict__ Whh = dir ? Whh_b : Whh_f;
    const float* __restrict__ P = &g_P[dir][0][0];
    float* __restrict__ hs = &g_h[dir][0][0];

    const int tid = threadIdx.x;
    const int u = tid >> 4, g = (tid >> 2) & 3, c = tid & 3;
    const int j0 = (int)myrank * UPB;
    const int r = g * 256 + j0 + u;          // gate row in [0,1024)

    // Weights for row r, cols [c*64, c*64+64), chunk-rotated by (kq+c)&15 so
    // the matching smem 16B reads are bank-conflict-free. Packed as f32x2.
    unsigned long long w2[32];
    {
        const ulonglong2* wrow = reinterpret_cast<const ulonglong2*>(Whh + (size_t)r * HDIM + c * 64);
#pragma unroll
        for (int kq = 0; kq < 16; kq++) {
            int ch = (kq + c) & 15;
            ulonglong2 t = wrow[ch];
            w2[2 * kq + 0] = t.x;
            w2[2 * kq + 1] = t.y;
        }
    }

    __shared__ __align__(16) float sh[2][HDIM];      // h double buffer (step-indexed)
    __shared__ __align__(16) float4 sgate[UPB];
    __shared__ __align__(8) unsigned long long mbar[2];

    const uint32_t mb0 = smem_u32(&mbar[0]);
    const uint32_t mb1 = smem_u32(&mbar[1]);

    if (tid == 0) {
        asm volatile("mbarrier.inval.shared.b64 [%0];" :: "r"(mb0) : "memory");
        asm volatile("mbarrier.inval.shared.b64 [%0];" :: "r"(mb1) : "memory");
        asm volatile("mbarrier.init.shared.b64 [%0], 1;" :: "r"(mb0) : "memory");
        asm volatile("mbarrier.init.shared.b64 [%0], 1;" :: "r"(mb1) : "memory");
        // Pre-post expected tx for h[0] (buf0) and h[1] (buf1) before any peer
        // can store: peers only start after the cluster sync below.
        asm volatile("mbarrier.arrive.expect_tx.shared.b64 _, [%0], %1;"
                     :: "r"(mb0), "r"((uint32_t)TXBYTES) : "memory");
        asm volatile("mbarrier.arrive.expect_tx.shared.b64 _, [%0], %1;"
                     :: "r"(mb1), "r"((uint32_t)TXBYTES) : "memory");
    }

    // Sender setup: 112 threads, dest peer = (myrank+1+(tid>>4))&7, pair = tid&15.
    const bool isSender = tid < 7 * 16;
    uint32_t s_ra0 = 0, s_ra1 = 0, s_rm0 = 0, s_rm1 = 0;
    const int sp = tid & 15;
    if (isSender) {
        uint32_t dst = (myrank + 1 + (uint32_t)(tid >> 4)) & 7;
        s_ra0 = mapa_rank(smem_u32(&sh[0][j0 + sp * 2]), dst);
        s_ra1 = mapa_rank(smem_u32(&sh[1][j0 + sp * 2]), dst);
        s_rm0 = mapa_rank(mb0, dst);
        s_rm1 = mapa_rank(mb1, dst);
    }

    __syncthreads();
    asm volatile("barrier.cluster.arrive.aligned;" ::: "memory");
    asm volatile("barrier.cluster.wait.aligned;" ::: "memory");

    float creg = 0.f;   // cell state, lanes tid<32 (unit = tid)

    for (int s = 0; s < LSEQ; s++) {
        const int pos = dir ? (LSEQ - 1 - s) : s;
        const int b = s & 1;

        // Prefetch input projection (independent of the sync).
        float pv = 0.f;
        if (c == 0) pv = __ldg(&P[(size_t)pos * G4 + r]);

        float part = 0.f;
        if (s > 0) {
            const int pb = (s - 1) & 1;
            const uint32_t parity = (uint32_t)((s - 1) >> 1) & 1u;
            mbar_wait_parity(pb ? mb1 : mb0, parity);

            // Post expected tx for h[s+1] on the barrier whose h[s-1] phase
            // just completed. Precedes our st.async of h[s], hence (causally)
            // any peer's st.async of h[s+1].
            if (tid == 0 && s + 1 < LSEQ) {
                asm volatile("mbarrier.arrive.expect_tx.shared.b64 _, [%0], %1;"
                             :: "r"(pb ? mb1 : mb0), "r"((uint32_t)TXBYTES) : "memory");
            }

            // Recurrent partial dot: 16 x 16B LDS + 32 packed f32x2 FMA.
            unsigned long long accA = 0ull, accB = 0ull;
            const ulonglong2* sh2 = reinterpret_cast<const ulonglong2*>(&sh[pb][c * 64]);
#pragma unroll
            for (int kq = 0; kq < 16; kq++) {
                int ch = (kq + c) & 15;
                ulonglong2 hv = sh2[ch];
                asm("fma.rn.f32x2 %0, %1, %2, %0;" : "+l"(accA) : "l"(w2[2 * kq + 0]), "l"(hv.x));
                asm("fma.rn.f32x2 %0, %1, %2, %0;" : "+l"(accB) : "l"(w2[2 * kq + 1]), "l"(hv.y));
            }
            unsigned long long accT;
            asm("add.rn.f32x2 %0, %1, %2;" : "=l"(accT) : "l"(accA), "l"(accB));
            part = __uint_as_float((uint32_t)accT) + __uint_as_float((uint32_t)(accT >> 32));
        }

        // Reduce across the 4 column-quarters (contiguous lanes).
        part += __shfl_down_sync(0xFFFFFFFFu, part, 2, 4);
        part += __shfl_down_sync(0xFFFFFFFFu, part, 1, 4);
        if (c == 0) reinterpret_cast<float*>(sgate)[u * 4 + g] = part + pv;
        __syncthreads();

        // Cell/hidden update; stage h locally (self copy) + global for feats.
        if (tid < UPB) {
            float4 gt = sgate[tid];
            creg = sig_fast(gt.y) * creg + sig_fast(gt.x) * tanh_fast(gt.z);
            float hv = sig_fast(gt.w) * tanh_fast(creg);
            sh[b][j0 + tid] = hv;
            hs[(size_t)pos * HDIM + j0 + tid] = hv;
        }
        __syncthreads();

        // Broadcast our 32 h values to the 7 peers; each 8B store bumps the
        // remote mbarrier tx count (data+signal fused, correctly ordered).
        if (isSender) {
            unsigned long long v =
                *reinterpret_cast<const unsigned long long*>(&sh[b][j0 + sp * 2]);
            asm volatile(
                "st.async.shared::cluster.mbarrier::complete_tx::bytes.b64 [%0], %1, [%2];"
                :: "r"(b ? s_ra1 : s_ra0), "l"(v), "r"(b ? s_rm1 : s_rm0) : "memory");
        }
    }
}

// ---------------------------------------------------------------------------
// feats[t][k] = [hf[t], hb[t]] . W_tag[k] + b_tag[k]
// ---------------------------------------------------------------------------
__global__ __launch_bounds__(64) void feats_kernel(
    const float* __restrict__ Wtag, const float* __restrict__ btag)
{
    __shared__ float shc[512];
    const int t = blockIdx.x;
    const int tid = threadIdx.x;
#pragma unroll
    for (int i = 0; i < 8; i++) {
        int d = tid + 64 * i;
        shc[d] = (d < HDIM) ? g_h[0][t][d] : g_h[1][t][d - HDIM];
    }
    __syncthreads();
    const int wr = tid >> 5, l = tid & 31;
#pragma unroll
    for (int kk = 0; kk < 5; kk++) {
        int k = wr * 5 + kk;
        float ssum = 0.f;
#pragma unroll
        for (int j = 0; j < 16; j++) {
            int d = l + 32 * j;
            ssum += shc[d] * Wtag[k * 512 + d];
        }
#pragma unroll
        for (int off = 16; off >= 1; off >>= 1)
            ssum += __shfl_down_sync(0xFFFFFFFFu, ssum, off);
        if (l == 0) g_feats[t][k] = ssum + btag[k];
    }
}

// ---------------------------------------------------------------------------
// Viterbi max-plus scan + traceback. One warp; backpointers in dynamic smem.
// Strict '>' argmax with ascending index == jnp.argmax first-max semantics.
// ---------------------------------------------------------------------------
__global__ void viterbi_kernel(const float* __restrict__ trans,
                               float* __restrict__ out, int out_size)
{
    extern __shared__ unsigned char bp[];   // [LSEQ][KTAG]
    const int lane = threadIdx.x;
    const int j = lane < KTAG ? lane : KTAG - 1;

    float Trow[KTAG];
#pragma unroll
    for (int p = 0; p < KTAG; p++) Trow[p] = trans[j * KTAG + p];

    float v = (lane == TAG_START) ? 0.f : -10000.f;
    float fc = g_feats[0][j];

    for (int t = 0; t < LSEQ; t++) {
        float fn = (t + 1 < LSEQ) ? g_feats[t + 1][j] : 0.f;   // prefetch
        float best = -3.4e38f;
        int arg = 0;
#pragma unroll
        for (int p = 0; p < KTAG; p++) {
            float vp = __shfl_sync(0xFFFFFFFFu, v, p);
            float cand = vp + Trow[p];
            if (cand > best) { best = cand; arg = p; }
        }
        if (lane < KTAG) bp[t * KTAG + lane] = (unsigned char)arg;
        v = best + fc;
        fc = fn;
    }

    float term = v + trans[TAG_STOP * KTAG + j];
    float bbest = -3.4e38f;
    int barg = 0;
#pragma unroll
    for (int p = 0; p < KTAG; p++) {
        float tp = __shfl_sync(0xFFFFFFFFu, term, p);
        if (tp > bbest) { bbest = tp; barg = p; }
    }
    __syncwarp();

    if (lane == 0) {
        if (out_size > 0) out[0] = bbest;                 // score
        int tag = barg;
        if (out_size > LSEQ) out[LSEQ] = (float)tag;      // path[L-1]
        for (int t = LSEQ - 1; t >= 1; t--) {
            tag = bp[t * KTAG + tag];
            if (out_size > t) out[t] = (float)tag;        // path[t-1] at index t
        }
    }
}

// ---------------------------------------------------------------------------
// Launch
// ---------------------------------------------------------------------------
extern "C" void kernel_launch(void* const* d_in, const int* in_sizes, int n_in,
                              void* d_out, int out_size)
{
    const int*   sent  = (const int*)  d_in[0];
    const float* emb   = (const float*)d_in[1];
    const float* Wih_f = (const float*)d_in[2];
    const float* Whh_f = (const float*)d_in[3];
    const float* bih_f = (const float*)d_in[4];
    const float* bhh_f = (const float*)d_in[5];
    const float* Wih_b = (const float*)d_in[6];
    const float* Whh_b = (const float*)d_in[7];
    const float* bih_b = (const float*)d_in[8];
    const float* bhh_b = (const float*)d_in[9];
    const float* W_tag = (const float*)d_in[10];
    const float* b_tag = (const float*)d_in[11];
    const float* trans = (const float*)d_in[12];
    float* out = (float*)d_out;

    cudaFuncSetAttribute(viterbi_kernel,
                         cudaFuncAttributeMaxDynamicSharedMemorySize,
                         LSEQ * KTAG);

    proj_kernel<<<dim3(LSEQ / 64, G4 / 64, 2), 256>>>(
        sent, emb, Wih_f, bih_f, bhh_f, Wih_b, bih_b, bhh_b);
    lstm_kernel<<<2 * NCTA, 512>>>(Whh_f, Whh_b);
    feats_kernel<<<LSEQ, 64>>>(W_tag, b_tag);
    viterbi_kernel<<<1, 32, LSEQ * KTAG>>>(trans, out, out_size);
}